// round 3
// baseline (speedup 1.0000x reference)
#include <cuda_runtime.h>
#include <math.h>
#include <stdint.h>

// ---------------------------------------------------------------------------
// Shapes (fixed by the problem)
// ---------------------------------------------------------------------------
#define LQ    1024      // sentence length
#define HIDQ  1024      // bidirectional hidden
#define HDIRQ 512       // per-direction hidden
#define DIN0  400       // WDIM + PDIM
#define MLPH  512       // MLP/2
#define G4H   2048      // 4 * HDIR

// Recurrence geometry: 128 CTAs (64/dir), 256 thr. CTA owns 8 h-elems
// (32 gate rows). Warp w <-> h-chunk [w*64, w*64+64); lane <-> gate row.
#define NCTA_DIR 64
#define JV       8

// ---------------------------------------------------------------------------
// Device scratch (no allocations allowed -> __device__ globals)
// ---------------------------------------------------------------------------
__device__ float g_emb[LQ * DIN0];
__device__ float g_xp[2 * LQ * G4H];
__device__ float g_hcat0[LQ * HIDQ];
__device__ float g_hcat1[LQ * HIDQ];
__device__ float g_featH[LQ * MLPH];
__device__ float g_featM[LQ * MLPH];
__device__ float g_shead[LQ];
__device__ float g_smodif[LQ];
__device__ int   g_flags[2 * NCTA_DIR];

__device__ __forceinline__ float fast_sigmoid(float x)
{
    return 1.f / (1.f + __expf(-x));
}
__device__ __forceinline__ float fast_tanh(float x)
{
    // tanh(x) = 2*sigmoid(2x) - 1 ; accurate to ~1e-6 rel with __expf
    float e = __expf(-2.f * x);
    return (1.f - e) / (1.f + e);
}

// ---------------------------------------------------------------------------
// Embedding gather
// ---------------------------------------------------------------------------
__global__ void embed_kernel(const int* __restrict__ wt, const int* __restrict__ pt,
                             const float* __restrict__ we, const float* __restrict__ pe)
{
    int l = blockIdx.x;
    int w = wt[l];
    int p = pt[l];
    for (int k = threadIdx.x; k < DIN0; k += blockDim.x) {
        float v;
        if (k < 300) v = we[(size_t)w * 300 + k];
        else         v = pe[(size_t)p * 100 + (k - 300)];
        g_emb[(size_t)l * DIN0 + k] = v;
    }
}

// ---------------------------------------------------------------------------
// SGEMM: C = A @ W^T + bias.  A:[M,K], W:[N,K] row-major.
// 128x64 tile, BK=16, 256 threads, 8x4 microtile. M%128==0, N%64==0, K%16==0.
// ---------------------------------------------------------------------------
#define BM 128
#define BN 64
#define BK 16
__global__ void __launch_bounds__(256)
sgemm_bias_kernel(const float* __restrict__ A, const float* __restrict__ W,
                  const float* __restrict__ bias, float* __restrict__ C,
                  int M, int N, int K,
                  long long sA, long long sW, long long sB, long long sC)
{
    int z = blockIdx.z;
    A    += (size_t)z * sA;
    W    += (size_t)z * sW;
    bias += (size_t)z * sB;
    C    += (size_t)z * sC;

    const int n0 = blockIdx.x * BN;
    const int m0 = blockIdx.y * BM;

    __shared__ float As[BK][BM];
    __shared__ float Ws[BK][BN];

    const int tid = threadIdx.x;
    const int tx  = tid & 15;          // n group (4 cols)
    const int ty  = tid >> 4;          // m group (8 rows)

    float acc[8][4];
#pragma unroll
    for (int i = 0; i < 8; i++)
#pragma unroll
        for (int j = 0; j < 4; j++) acc[i][j] = 0.f;

    for (int k0 = 0; k0 < K; k0 += BK) {
#pragma unroll
        for (int s = 0; s < 8; s++) {
            int idx = tid + s * 256;           // 2048 A elements
            int col = idx & 15, row = idx >> 4;
            As[col][row] = A[(size_t)(m0 + row) * K + k0 + col];
        }
#pragma unroll
        for (int s = 0; s < 4; s++) {
            int idx = tid + s * 256;           // 1024 W elements
            int col = idx & 15, row = idx >> 4;
            Ws[col][row] = W[(size_t)(n0 + row) * K + k0 + col];
        }
        __syncthreads();
#pragma unroll
        for (int k = 0; k < BK; k++) {
            float a[8], b[4];
#pragma unroll
            for (int i = 0; i < 8; i++) a[i] = As[k][ty * 8 + i];
#pragma unroll
            for (int j = 0; j < 4; j++) b[j] = Ws[k][tx * 4 + j];
#pragma unroll
            for (int i = 0; i < 8; i++)
#pragma unroll
                for (int j = 0; j < 4; j++) acc[i][j] = fmaf(a[i], b[j], acc[i][j]);
        }
        __syncthreads();
    }

#pragma unroll
    for (int i = 0; i < 8; i++) {
        int m = m0 + ty * 8 + i;
        int n = n0 + tx * 4;
        float4 o;
        o.x = acc[i][0] + bias[n + 0];
        o.y = acc[i][1] + bias[n + 1];
        o.z = acc[i][2] + bias[n + 2];
        o.w = acc[i][3] + bias[n + 3];
        *(float4*)&C[(size_t)m * N + n] = o;
    }
}

// ---------------------------------------------------------------------------
// Flag reset before each recurrence launch (graph-replay safe)
// ---------------------------------------------------------------------------
__global__ void reset_flags_kernel()
{
    if (threadIdx.x < 2 * NCTA_DIR) g_flags[threadIdx.x] = 0;
}

// ---------------------------------------------------------------------------
// Persistent bidirectional LSTM layer, register-resident Whh slice.
// CTA b: dir d=b>>6, slice cb=b&63 owns h[j0..j0+8) (j0=cb*8).
// Thread (warp w, lane l): weights Whh[row(l)][w*64 .. w*64+64) in registers,
// where row(l) = gate(l>>3)*512 + j0 + (l&7).
// Per step, warp w: poll 8 chunk-producer flags (acquire), load 64 h values,
// 64 FFMA, write partial; bar; warp0 reduces, computes gates, publishes h and
// releases flag. Partial/xp buffers are step-parity double-buffered so only
// one __syncthreads per step is needed.
// ---------------------------------------------------------------------------
__global__ void __launch_bounds__(256, 1)
lstm_layer_kernel(const float* __restrict__ Whh,   // [2][2048][512]
                  const float* __restrict__ xp,    // [2][L][2048] (bias folded in)
                  float* __restrict__ hcat)        // [L][1024]
{
    __shared__ float h_s[8][64];        // per-warp h chunk staging
    __shared__ float part[2][8][32];    // per-warp partial sums (parity)
    __shared__ float xp_s[2][32];       // xp for 32 rows (parity)

    const int tid  = threadIdx.x;
    const int wid  = tid >> 5;
    const int lane = tid & 31;
    const int b    = blockIdx.x;
    const int d    = b >> 6;
    const int cb   = b & 63;
    const int j0   = cb * JV;

    // --- stage this thread's 64 weights into registers ---
    float4 wr[16];
    {
        const int gate = lane >> 3, jl = lane & 7;
        const float4* src = (const float4*)(Whh +
            ((size_t)d * G4H + (size_t)gate * HDIRQ + j0 + jl) * HDIRQ + wid * 64);
#pragma unroll
        for (int i = 0; i < 16; i++) wr[i] = src[i];
    }

    float c_state = 0.f;                               // lanes 0..7 of warp 0
    int* const myflag = g_flags + d * NCTA_DIR + cb;
    const int* const pollp = g_flags + d * NCTA_DIR + (wid << 3) + (lane & 7);

    for (int step = 0; step < LQ; step++) {
        const int t = (d == 0) ? step : (LQ - 1 - step);
        const int p = step & 1;

        // prefetch xp (warp 1), issued before the poll so latency overlaps
        float xpv = 0.f;
        if (wid == 1) {
            const int gate = lane >> 3, jl = lane & 7;
            xpv = __ldg(xp + ((size_t)d * LQ + t) * G4H +
                        (size_t)gate * HDIRQ + j0 + jl);
        }

        float acc = 0.f;
        if (step > 0) {
            // wait for this warp's 8 chunk producers (acquire); first probe is
            // immediate, subsequent probes back off to bound flag L2 traffic
            int miss = 0;
            for (;;) {
                int v = step;
                if (lane < 8)
                    asm volatile("ld.acquire.gpu.global.s32 %0, [%1];"
                                 : "=r"(v) : "l"(pollp));
                if (__all_sync(0xffffffffu, v >= step)) break;
                if (miss++) __nanosleep(32);
            }
            const int tp = (d == 0) ? (t - 1) : (t + 1);
            float2 hv = *(const float2*)(hcat + (size_t)tp * HIDQ + d * HDIRQ +
                                         (wid << 6) + lane * 2);
            ((float2*)h_s[wid])[lane] = hv;
            __syncwarp();
            const float4* hs4 = (const float4*)h_s[wid];
#pragma unroll
            for (int i = 0; i < 16; i++) {
                float4 hb = hs4[i];
                acc = fmaf(wr[i].x, hb.x, acc);
                acc = fmaf(wr[i].y, hb.y, acc);
                acc = fmaf(wr[i].z, hb.z, acc);
                acc = fmaf(wr[i].w, hb.w, acc);
            }
        }

        if (wid == 1) xp_s[p][lane] = xpv;
        part[p][wid][lane] = acc;
        __syncthreads();

        if (wid == 0) {
            float tot = 0.f;
#pragma unroll
            for (int w = 0; w < 8; w++) tot += part[p][w][lane];
            const int jj = lane & 7;
            float gi = __shfl_sync(0xffffffffu, tot, jj);
            float gf = __shfl_sync(0xffffffffu, tot, jj + 8);
            float gg = __shfl_sync(0xffffffffu, tot, jj + 16);
            float go = __shfl_sync(0xffffffffu, tot, jj + 24);
            if (lane < 8) {
                gi += xp_s[p][jj];
                gf += xp_s[p][8 + jj];
                gg += xp_s[p][16 + jj];
                go += xp_s[p][24 + jj];
                float iv = fast_sigmoid(gi);
                float fv = fast_sigmoid(gf);
                float gv = fast_tanh(gg);
                float ov = fast_sigmoid(go);
                c_state = fv * c_state + iv * gv;
                float hv = ov * fast_tanh(c_state);
                hcat[(size_t)t * HIDQ + d * HDIRQ + j0 + lane] = hv;
            }
            __syncwarp();
            if (lane == 0) {
                int nv = step + 1;
                asm volatile("st.release.gpu.global.s32 [%0], %1;"
                             :: "l"(myflag), "r"(nv) : "memory");
            }
        }
    }
}

// ---------------------------------------------------------------------------
// s[l] = sum_n tanh(feat[l][n]) * wo[off + n]
// ---------------------------------------------------------------------------
__global__ void reduce_s_kernel(const float* __restrict__ feat, const float* __restrict__ wo,
                                int off, float* __restrict__ s)
{
    int l = blockIdx.x;
    int tid = threadIdx.x;
    float p = 0.f;
    for (int n = tid; n < MLPH; n += 256)
        p += tanhf(feat[(size_t)l * MLPH + n]) * wo[off + n];
    __shared__ float red[8];
#pragma unroll
    for (int o = 16; o > 0; o >>= 1) p += __shfl_xor_sync(0xffffffffu, p, o);
    if ((tid & 31) == 0) red[tid >> 5] = p;
    __syncthreads();
    if (tid < 8) {
        float v = red[tid];
#pragma unroll
        for (int o = 4; o > 0; o >>= 1) v += __shfl_xor_sync(0xffu, v, o);
        if (tid == 0) s[l] = v;
    }
}

// ---------------------------------------------------------------------------
// score[m][h] = s_modif[m] + s_head[h] + bo
// ---------------------------------------------------------------------------
__global__ void score_kernel(const float* __restrict__ sh, const float* __restrict__ sm,
                             const float* __restrict__ bo, float* __restrict__ out)
{
    int idx = blockIdx.x * 256 + threadIdx.x;
    int m = idx >> 10;
    int h = idx & 1023;
    out[idx] = sm[m] + sh[h] + bo[0];
}

// ---------------------------------------------------------------------------
// Launch sequence (graph-capturable)
// ---------------------------------------------------------------------------
extern "C" void kernel_launch(void* const* d_in, const int* in_sizes, int n_in,
                              void* d_out, int out_size)
{
    (void)in_sizes; (void)n_in; (void)out_size;

    const int*   wt   = (const int*)  d_in[0];
    const int*   pt   = (const int*)  d_in[1];
    const float* we   = (const float*)d_in[2];
    const float* pe   = (const float*)d_in[3];
    const float* Wih0 = (const float*)d_in[4];
    const float* Whh0 = (const float*)d_in[5];
    const float* b0   = (const float*)d_in[6];
    const float* Wih1 = (const float*)d_in[7];
    const float* Whh1 = (const float*)d_in[8];
    const float* b1   = (const float*)d_in[9];
    const float* Wh   = (const float*)d_in[10];
    const float* bh   = (const float*)d_in[11];
    const float* Wm   = (const float*)d_in[12];
    const float* bm   = (const float*)d_in[13];
    const float* wo   = (const float*)d_in[14];
    const float* bo   = (const float*)d_in[15];
    float*       out  = (float*)d_out;

    float *p_emb, *p_xp, *p_h0, *p_h1, *p_fH, *p_fM, *p_sh, *p_sm;
    cudaGetSymbolAddress((void**)&p_emb, g_emb);
    cudaGetSymbolAddress((void**)&p_xp,  g_xp);
    cudaGetSymbolAddress((void**)&p_h0,  g_hcat0);
    cudaGetSymbolAddress((void**)&p_h1,  g_hcat1);
    cudaGetSymbolAddress((void**)&p_fH,  g_featH);
    cudaGetSymbolAddress((void**)&p_fM,  g_featM);
    cudaGetSymbolAddress((void**)&p_sh,  g_shead);
    cudaGetSymbolAddress((void**)&p_sm,  g_smodif);

    // 1) embeddings
    embed_kernel<<<LQ, 128>>>(wt, pt, we, pe);

    // 2) layer-0 input projections
    {
        dim3 g(G4H / BN, LQ / BM, 2);
        sgemm_bias_kernel<<<g, 256>>>(p_emb, Wih0, b0, p_xp,
                                      LQ, G4H, DIN0,
                                      0LL, (long long)G4H * DIN0, (long long)G4H,
                                      (long long)LQ * G4H);
    }

    // 3) layer-0 recurrence
    reset_flags_kernel<<<1, 128>>>();
    lstm_layer_kernel<<<2 * NCTA_DIR, 256>>>(Whh0, p_xp, p_h0);

    // 4) layer-1 input projections
    {
        dim3 g(G4H / BN, LQ / BM, 2);
        sgemm_bias_kernel<<<g, 256>>>(p_h0, Wih1, b1, p_xp,
                                      LQ, G4H, HIDQ,
                                      0LL, (long long)G4H * HIDQ, (long long)G4H,
                                      (long long)LQ * G4H);
    }

    // 5) layer-1 recurrence
    reset_flags_kernel<<<1, 128>>>();
    lstm_layer_kernel<<<2 * NCTA_DIR, 256>>>(Whh1, p_xp, p_h1);

    // 6) MLP head features
    {
        dim3 g(MLPH / BN, LQ / BM, 1);
        sgemm_bias_kernel<<<g, 256>>>(p_h1, Wh, bh, p_fH, LQ, MLPH, HIDQ, 0LL, 0LL, 0LL, 0LL);
        sgemm_bias_kernel<<<g, 256>>>(p_h1, Wm, bm, p_fM, LQ, MLPH, HIDQ, 0LL, 0LL, 0LL, 0LL);
    }

    // 7) tanh-dot reductions
    reduce_s_kernel<<<LQ, 256>>>(p_fH, wo, 0,    p_sh);
    reduce_s_kernel<<<LQ, 256>>>(p_fM, wo, MLPH, p_sm);

    // 8) broadcast score matrix
    score_kernel<<<(LQ * LQ) / 256, 256>>>(p_sh, p_sm, bo, out);
}